// round 10
// baseline (speedup 1.0000x reference)
#include <cuda_runtime.h>
#include <cstdint>

#define B_ 32
#define S_ 1024
#define D_ 512
#define SCALE 0.044194173824159216f   // 1/sqrt(512)

// Fallback scratch in case out_size does not include the attn_sm output.
__device__ float g_attn_scratch[(size_t)B_ * S_ * S_];

__device__ __forceinline__ void mma_tf32(float* c, const uint32_t* a, const uint32_t* b) {
    asm volatile(
        "mma.sync.aligned.m16n8k8.row.col.f32.tf32.tf32.f32 "
        "{%0,%1,%2,%3}, {%4,%5,%6,%7}, {%8,%9}, {%0,%1,%2,%3};\n"
        : "+f"(c[0]), "+f"(c[1]), "+f"(c[2]), "+f"(c[3])
        : "r"(a[0]), "r"(a[1]), "r"(a[2]), "r"(a[3]),
          "r"(b[0]), "r"(b[1]));
}
__device__ __forceinline__ void ldsm4(uint32_t& r0, uint32_t& r1, uint32_t& r2, uint32_t& r3, uint32_t a) {
    asm volatile("ldmatrix.sync.aligned.m8n8.x4.shared.b16 {%0,%1,%2,%3}, [%4];"
                 : "=r"(r0), "=r"(r1), "=r"(r2), "=r"(r3) : "r"(a));
}
__device__ __forceinline__ void ldsm2(uint32_t& r0, uint32_t& r1, uint32_t a) {
    asm volatile("ldmatrix.sync.aligned.m8n8.x2.shared.b16 {%0,%1}, [%2];"
                 : "=r"(r0), "=r"(r1) : "r"(a));
}

// ---------------------------------------------------------------------------
// Kernel 1: masked_vec = (Q K^T)*SCALE*mask.  128x128 tile, BK=32,
// 3-stage smem ring. Producer: LDG -> +0x1000 (rna into tf32 boundary, ALU
// pipe) -> STS. Consumer: ldmatrix + mma.sync, ZERO cvt in the inner loop.
// ---------------------------------------------------------------------------
__global__ __launch_bounds__(256, 2) void qk_kernel(
    const float* __restrict__ Q, const float* __restrict__ K,
    const int* __restrict__ rep, float* __restrict__ attn_param)
{
    float* attn = attn_param ? attn_param : g_attn_scratch;
    const int bm = blockIdx.y, bn = blockIdx.x, b = blockIdx.z;
    const int m0 = bm * 128, n0 = bn * 128;
    const int tid = threadIdx.x;
    float* attn_b = attn + (size_t)b * S_ * S_;

    if (bn > bm) {
        float4 z = make_float4(0.f, 0.f, 0.f, 0.f);
        #pragma unroll
        for (int i = 0; i < 16; i++) {
            int idx = tid + i * 256;
            int r = idx >> 5, c = idx & 31;
            reinterpret_cast<float4*>(attn_b + (size_t)(m0 + r) * S_ + n0)[c] = z;
        }
        return;
    }

    extern __shared__ float smem[];              // 3 stages x 32KB
    const uint32_t smem_u = (uint32_t)__cvta_generic_to_shared(smem);

    const int warp = tid >> 5, lane = tid & 31;
    const int wm = warp & 1, wn = warp >> 1;
    const int gID = lane >> 2, tig = lane & 3;

    const float* Qb = Q + ((size_t)b * S_ + m0) * D_;
    const float* Kb = K + ((size_t)b * S_ + n0) * D_;

    // producer mapping: 16B granules, XOR swizzle
    const int lr = tid >> 3, lc4 = tid & 7;
    const uint32_t sw_off = (uint32_t)((lc4 ^ (lr & 7)) << 4);

    // ldmatrix lane address components
    const int a_ro = (lane & 7) + ((lane >> 4) << 3);
    const int a_ck = (lane >> 3) & 1;
    const int l7 = lane & 7;

    float acc[4][4][4];
    #pragma unroll
    for (int i = 0; i < 4; i++)
        #pragma unroll
        for (int j = 0; j < 4; j++)
            #pragma unroll
            for (int r = 0; r < 4; r++) acc[i][j][r] = 0.f;

    uint4 qr[4], kr[4];

    #define QK_LDG(kk) do {                                                    \
        _Pragma("unroll")                                                      \
        for (int i_ = 0; i_ < 4; i_++) {                                       \
            int r_ = lr + i_ * 32;                                             \
            qr[i_] = *reinterpret_cast<const uint4*>(Qb + (size_t)r_ * D_ + (kk) + lc4 * 4); \
            kr[i_] = *reinterpret_cast<const uint4*>(Kb + (size_t)r_ * D_ + (kk) + lc4 * 4); \
        }                                                                      \
    } while (0)

    #define QK_STS(st) do {                                                    \
        uint32_t bA_ = smem_u + (uint32_t)(st) * 32768u;                       \
        uint32_t bB_ = bA_ + 16384u;                                           \
        _Pragma("unroll")                                                      \
        for (int i_ = 0; i_ < 4; i_++) {                                       \
            int r_ = lr + i_ * 32;                                             \
            uint32_t off_ = (uint32_t)(r_ * 128) + sw_off;                     \
            asm volatile("st.shared.v4.b32 [%0], {%1,%2,%3,%4};" ::            \
                "r"(bA_ + off_), "r"(qr[i_].x + 0x1000u), "r"(qr[i_].y + 0x1000u), \
                "r"(qr[i_].z + 0x1000u), "r"(qr[i_].w + 0x1000u) : "memory");  \
            asm volatile("st.shared.v4.b32 [%0], {%1,%2,%3,%4};" ::            \
                "r"(bB_ + off_), "r"(kr[i_].x + 0x1000u), "r"(kr[i_].y + 0x1000u), \
                "r"(kr[i_].z + 0x1000u), "r"(kr[i_].w + 0x1000u) : "memory");  \
        }                                                                      \
    } while (0)

    // Prologue: stage0 filled; regs hold tile 1.
    QK_LDG(0);
    QK_STS(0);
    QK_LDG(32);
    __syncthreads();

    for (int t = 0; t < 16; t++) {
        const uint32_t bA = smem_u + (uint32_t)(t % 3) * 32768u;
        const uint32_t bB = bA + 16384u;

        // stage (t+1)%3 is free (last consumed at t-2): stage it now
        if (t + 1 < 16) {
            QK_STS((t + 1) % 3);
            if (t + 2 < 16) QK_LDG((t + 2) * 32);
        }

        #pragma unroll
        for (int ks = 0; ks < 4; ks++) {
            uint32_t bf[4][2];
            #pragma unroll
            for (int in_ = 0; in_ < 4; in_++) {
                int n = wn * 32 + in_ * 8 + l7;
                uint32_t addr = bB + (uint32_t)(n * 128)
                              + (uint32_t)(((((ks << 1) + a_ck) ^ l7)) << 4);
                ldsm2(bf[in_][0], bf[in_][1], addr);
            }
            #pragma unroll
            for (int im = 0; im < 4; im++) {
                int r = wm * 64 + im * 16 + a_ro;
                uint32_t addr = bA + (uint32_t)(r * 128)
                              + (uint32_t)(((((ks << 1) + a_ck) ^ l7)) << 4);
                uint32_t r0, r1, r2, r3;
                ldsm4(r0, r1, r2, r3, addr);
                uint32_t a[4] = { r0, r2, r1, r3 };
                #pragma unroll
                for (int in_ = 0; in_ < 4; in_++)
                    mma_tf32(acc[im][in_], a, bf[in_]);
            }
        }
        __syncthreads();
    }
    #undef QK_LDG
    #undef QK_STS

    // Epilogue: scale + mask, write masked_vec.
    const int* repb = rep + b * S_;
    #pragma unroll
    for (int im = 0; im < 4; im++) {
        int mA = m0 + wm * 64 + im * 16 + gID;
        int mB = mA + 8;
        int rqA = repb[mA], rqB = repb[mB];
        #pragma unroll
        for (int in_ = 0; in_ < 4; in_++) {
            int n = n0 + wn * 32 + in_ * 8 + tig * 2;
            int rk0 = repb[n], rk1 = repb[n + 1];
            float v00 = acc[im][in_][0] * SCALE;
            float v01 = acc[im][in_][1] * SCALE;
            float v10 = acc[im][in_][2] * SCALE;
            float v11 = acc[im][in_][3] * SCALE;
            attn_b[(size_t)mA * S_ + n]     = (n     < mA && rqA && rk0) ? v00 : 0.f;
            attn_b[(size_t)mA * S_ + n + 1] = (n + 1 < mA && rqA && rk1) ? v01 : 0.f;
            attn_b[(size_t)mB * S_ + n]     = (n     < mB && rqB && rk0) ? v10 : 0.f;
            attn_b[(size_t)mB * S_ + n + 1] = (n + 1 < mB && rqB && rk1) ? v11 : 0.f;
        }
    }
}

// ---------------------------------------------------------------------------
// Kernel 2: in-place row softmax, faithful to reference semantics.
// ---------------------------------------------------------------------------
__global__ __launch_bounds__(256) void softmax_kernel(
    float* attn_param, const int* __restrict__ rep)
{
    float* attn = attn_param ? attn_param : g_attn_scratch;
    const int q = blockIdx.x, b = blockIdx.y;
    float* row = attn + ((size_t)b * S_ + q) * S_;
    const int tid = threadIdx.x;

    float4 v = reinterpret_cast<float4*>(row)[tid];
    const int k0 = tid * 4;
    const int rq = rep[b * S_ + q];
    const int4 rk = reinterpret_cast<const int4*>(rep + b * S_)[tid];

    __shared__ float red_max[8];
    __shared__ float red_sum[8];

    float mx = fmaxf(fmaxf(v.x, v.y), fmaxf(v.z, v.w));
    #pragma unroll
    for (int o = 16; o; o >>= 1) mx = fmaxf(mx, __shfl_xor_sync(0xffffffffu, mx, o));
    if ((tid & 31) == 0) red_max[tid >> 5] = mx;
    __syncthreads();
    mx = red_max[0];
    #pragma unroll
    for (int w = 1; w < 8; w++) mx = fmaxf(mx, red_max[w]);

    const bool m0b = (k0     < q) && rq && rk.x;
    const bool m1b = (k0 + 1 < q) && rq && rk.y;
    const bool m2b = (k0 + 2 < q) && rq && rk.z;
    const bool m3b = (k0 + 3 < q) && rq && rk.w;
    float e0 = m0b ? __expf(v.x - mx) : 0.f;
    float e1 = m1b ? __expf(v.y - mx) : 0.f;
    float e2 = m2b ? __expf(v.z - mx) : 0.f;
    float e3 = m3b ? __expf(v.w - mx) : 0.f;

    float sden = (e0 + e1) + (e2 + e3);
    #pragma unroll
    for (int o = 16; o; o >>= 1) sden += __shfl_xor_sync(0xffffffffu, sden, o);
    if ((tid & 31) == 0) red_sum[tid >> 5] = sden;
    __syncthreads();
    sden = red_sum[0];
    #pragma unroll
    for (int w = 1; w < 8; w++) sden += red_sum[w];

    float s2 = sden + ((sden == 0.f) ? 1.f : 0.f);
    float inv = 1.f / (s2 + 1e-20f);

    v.x = e0 * inv; v.y = e1 * inv; v.z = e2 * inv; v.w = e3 * inv;
    reinterpret_cast<float4*>(row)[tid] = v;
}

// ---------------------------------------------------------------------------
// Kernel 3: out = attn_sm @ V.  Triangular K-loop, same producer scheme
// (LDG -> +0x1000 -> STS), zero cvt in the consumer.
// V stored [k][n] stride 136 floats (conflict-free for the B fragment reads).
// ---------------------------------------------------------------------------
__global__ __launch_bounds__(256, 2) void pv_kernel(
    const float* attn_param, const float* __restrict__ V, float* __restrict__ out)
{
    const float* attn = attn_param ? attn_param : g_attn_scratch;
    const int bm = blockIdx.y, bn = blockIdx.x, b = blockIdx.z;
    const int m0 = bm * 128, n0 = bn * 128;
    const int tid = threadIdx.x;

    extern __shared__ float smem[];              // 3 stages x 33792B
    const uint32_t smem_u = (uint32_t)__cvta_generic_to_shared(smem);

    const int warp = tid >> 5, lane = tid & 31;
    const int wm = warp & 1, wn = warp >> 1;
    const int gID = lane >> 2, tig = lane & 3;

    const float* Ab = attn + ((size_t)b * S_ + m0) * S_;
    const float* Vb = V + (size_t)b * S_ * D_;

    const int lr = tid >> 3, lc4 = tid & 7;
    const uint32_t sw_off = (uint32_t)((lc4 ^ (lr & 7)) << 4);
    const int vrow = tid >> 5, vcol = tid & 31;

    const int a_ro = (lane & 7) + ((lane >> 4) << 3);
    const int a_ck = (lane >> 3) & 1;
    const int l7 = lane & 7;

    float acc[4][4][4];
    #pragma unroll
    for (int i = 0; i < 4; i++)
        #pragma unroll
        for (int j = 0; j < 4; j++)
            #pragma unroll
            for (int r = 0; r < 4; r++) acc[i][j][r] = 0.f;

    const int NT = (bm + 1) * 4;   // k-tiles of 32, strictly-lower-tri bound

    uint4 ar[4], vr[4];

    #define PV_LDG(kk) do {                                                    \
        _Pragma("unroll")                                                      \
        for (int i_ = 0; i_ < 4; i_++) {                                       \
            int r_ = lr + i_ * 32;                                             \
            ar[i_] = *reinterpret_cast<const uint4*>(Ab + (size_t)r_ * S_ + (kk) + lc4 * 4); \
            int rv_ = vrow + i_ * 8;                                           \
            vr[i_] = *reinterpret_cast<const uint4*>(Vb + (size_t)((kk) + rv_) * D_ + n0 + vcol * 4); \
        }                                                                      \
    } while (0)

    #define PV_STS(st) do {                                                    \
        uint32_t bA_ = smem_u + (uint32_t)(st) * 33792u;                       \
        uint32_t bB_ = bA_ + 16384u;                                           \
        _Pragma("unroll")                                                      \
        for (int i_ = 0; i_ < 4; i_++) {                                       \
            int r_ = lr + i_ * 32;                                             \
            asm volatile("st.shared.v4.b32 [%0], {%1,%2,%3,%4};" ::            \
                "r"(bA_ + (uint32_t)(r_ * 128) + sw_off),                      \
                "r"(ar[i_].x + 0x1000u), "r"(ar[i_].y + 0x1000u),              \
                "r"(ar[i_].z + 0x1000u), "r"(ar[i_].w + 0x1000u) : "memory");  \
            int rv_ = vrow + i_ * 8;                                           \
            asm volatile("st.shared.v4.b32 [%0], {%1,%2,%3,%4};" ::            \
                "r"(bB_ + (uint32_t)((rv_ * 136 + vcol * 4) * 4)),             \
                "r"(vr[i_].x + 0x1000u), "r"(vr[i_].y + 0x1000u),              \
                "r"(vr[i_].z + 0x1000u), "r"(vr[i_].w + 0x1000u) : "memory");  \
        }                                                                      \
    } while (0)

    PV_LDG(0);
    PV_STS(0);
    if (NT > 1) PV_LDG(32);
    __syncthreads();

    for (int t = 0; t < NT; t++) {
        const uint32_t bA = smem_u + (uint32_t)(t % 3) * 33792u;
        const float* Vs = smem + (size_t)(t % 3) * 8448 + 4096;

        if (t + 1 < NT) {
            PV_STS((t + 1) % 3);
            if (t + 2 < NT) PV_LDG((t + 2) * 32);
        }

        #pragma unroll
        for (int ks = 0; ks < 4; ks++) {
            uint32_t bf[4][2];
            #pragma unroll
            for (int in_ = 0; in_ < 4; in_++) {
                int nn = wn * 32 + in_ * 8 + gID;
                bf[in_][0] = __float_as_uint(Vs[(ks * 8 + tig) * 136 + nn]);
                bf[in_][1] = __float_as_uint(Vs[(ks * 8 + 4 + tig) * 136 + nn]);
            }
            #pragma unroll
            for (int im = 0; im < 4; im++) {
                int r = wm * 64 + im * 16 + a_ro;
                uint32_t addr = bA + (uint32_t)(r * 128)
                              + (uint32_t)(((((ks << 1) + a_ck) ^ l7)) << 4);
                uint32_t r0, r1, r2, r3;
                ldsm4(r0, r1, r2, r3, addr);
                uint32_t a[4] = { r0, r2, r1, r3 };
                #pragma unroll
                for (int in_ = 0; in_ < 4; in_++)
                    mma_tf32(acc[im][in_], a, bf[in_]);
            }
        }
        __syncthreads();
    }
    #undef PV_LDG
    #undef PV_STS

    #pragma unroll
    for (int im = 0; im < 4; im++) {
        int mA = m0 + wm * 64 + im * 16 + gID;
        int mB = mA + 8;
        #pragma unroll
        for (int in_ = 0; in_ < 4; in_++) {
            int n = n0 + wn * 32 + in_ * 8 + tig * 2;
            out[((size_t)b * S_ + mA) * D_ + n]     = acc[im][in_][0];
            out[((size_t)b * S_ + mA) * D_ + n + 1] = acc[im][in_][1];
            out[((size_t)b * S_ + mB) * D_ + n]     = acc[im][in_][2];
            out[((size_t)b * S_ + mB) * D_ + n + 1] = acc[im][in_][3];
        }
    }
}

extern "C" void kernel_launch(void* const* d_in, const int* in_sizes, int n_in,
                              void* d_out, int out_size)
{
    const float* q   = (const float*)d_in[0];
    const float* k   = (const float*)d_in[1];
    const float* v   = (const float*)d_in[2];
    const int*   rep = (const int*)d_in[3];
    float* out = (float*)d_out;

    const long OUT_ELEMS  = (long)B_ * S_ * D_;   // 16,777,216
    const long ATTN_ELEMS = (long)B_ * S_ * S_;   // 33,554,432

    float* attn = nullptr;  // nullptr -> kernels fall back to g_attn_scratch
    if ((long)out_size >= OUT_ELEMS + ATTN_ELEMS)
        attn = out + OUT_ELEMS;

    const int QK_SMEM = 3 * 32768;   // 98304 B
    const int PV_SMEM = 3 * 33792;   // 101376 B
    cudaFuncSetAttribute(qk_kernel, cudaFuncAttributeMaxDynamicSharedMemorySize, QK_SMEM);
    cudaFuncSetAttribute(pv_kernel, cudaFuncAttributeMaxDynamicSharedMemorySize, PV_SMEM);

    dim3 g1(8, 8, B_);
    qk_kernel<<<g1, 256, QK_SMEM>>>(q, k, rep, attn);

    dim3 g2(S_, B_);
    softmax_kernel<<<g2, 256>>>(attn, rep);

    dim3 g3(4, 8, B_);
    pv_kernel<<<g3, 256, PV_SMEM>>>(attn, v, out);
}

// round 13
// speedup vs baseline: 1.3639x; 1.3639x over previous
#include <cuda_runtime.h>
#include <cuda_fp16.h>
#include <cstdint>

#define B_ 32
#define S_ 1024
#define D_ 512
#define SCALE 0.044194173824159216f   // 1/sqrt(512)

// Fallback scratch in case out_size does not include the attn_sm output.
__device__ float g_attn_scratch[(size_t)B_ * S_ * S_];

// pack two f32 -> f16x2 (lo = first element), round-to-nearest
__device__ __forceinline__ uint32_t f2h2(float lo, float hi) {
    uint32_t r;
    asm("cvt.rn.f16x2.f32 %0, %1, %2;" : "=r"(r) : "f"(hi), "f"(lo));
    return r;
}

__device__ __forceinline__ void mma_f16(float* c, const uint32_t* a, const uint32_t* b) {
    asm volatile(
        "mma.sync.aligned.m16n8k16.row.col.f32.f16.f16.f32 "
        "{%0,%1,%2,%3}, {%4,%5,%6,%7}, {%8,%9}, {%0,%1,%2,%3};\n"
        : "+f"(c[0]), "+f"(c[1]), "+f"(c[2]), "+f"(c[3])
        : "r"(a[0]), "r"(a[1]), "r"(a[2]), "r"(a[3]),
          "r"(b[0]), "r"(b[1]));
}
__device__ __forceinline__ void ldsm4(uint32_t& r0, uint32_t& r1, uint32_t& r2, uint32_t& r3, uint32_t a) {
    asm volatile("ldmatrix.sync.aligned.m8n8.x4.shared.b16 {%0,%1,%2,%3}, [%4];"
                 : "=r"(r0), "=r"(r1), "=r"(r2), "=r"(r3) : "r"(a));
}
__device__ __forceinline__ void ldsm2(uint32_t& r0, uint32_t& r1, uint32_t a) {
    asm volatile("ldmatrix.sync.aligned.m8n8.x2.shared.b16 {%0,%1}, [%2];"
                 : "=r"(r0), "=r"(r1) : "r"(a));
}
__device__ __forceinline__ void ldsm2t(uint32_t& r0, uint32_t& r1, uint32_t a) {
    asm volatile("ldmatrix.sync.aligned.m8n8.x2.trans.shared.b16 {%0,%1}, [%2];"
                 : "=r"(r0), "=r"(r1) : "r"(a));
}

// ---------------------------------------------------------------------------
// Kernel 1: masked_vec = (Q K^T)*SCALE*mask.  128x128 tile, BK=64 (f32 cols),
// fp16 m16n8k16 MMA, 3-stage smem ring (16KB/operand/stage), producer does
// LDG f32 -> cvt f16x2 -> STS (swizzled 16B granules).
// ---------------------------------------------------------------------------
__global__ __launch_bounds__(256, 2) void qk_kernel(
    const float* __restrict__ Q, const float* __restrict__ K,
    const int* __restrict__ rep, float* __restrict__ attn_param)
{
    float* attn = attn_param ? attn_param : g_attn_scratch;
    const int bm = blockIdx.y, bn = blockIdx.x, b = blockIdx.z;
    const int m0 = bm * 128, n0 = bn * 128;
    const int tid = threadIdx.x;
    float* attn_b = attn + (size_t)b * S_ * S_;

    if (bn > bm) {
        float4 z = make_float4(0.f, 0.f, 0.f, 0.f);
        #pragma unroll
        for (int i = 0; i < 16; i++) {
            int idx = tid + i * 256;
            int r = idx >> 5, c = idx & 31;
            reinterpret_cast<float4*>(attn_b + (size_t)(m0 + r) * S_ + n0)[c] = z;
        }
        return;
    }

    extern __shared__ float smem[];              // 3 stages x 32KB (A16K + B16K)
    const uint32_t smem_u = (uint32_t)__cvta_generic_to_shared(smem);

    const int warp = tid >> 5, lane = tid & 31;
    const int wm = warp & 1, wn = warp >> 1;
    const int gID = lane >> 2, tig = lane & 3;

    const float* Qb = Q + ((size_t)b * S_ + m0) * D_;
    const float* Kb = K + ((size_t)b * S_ + n0) * D_;

    // producer: 8 threads per row (32B f32 each), rows lr+32i, chunk = lc
    const int lr = tid >> 3, lc = tid & 7;
    const uint32_t psw = (uint32_t)((lc ^ (lr & 7)) << 4);

    const int l7 = lane & 7;
    const int lb1 = (lane >> 3) & 1;
    const int lb2 = lane >> 4;

    float acc[4][4][4];
    #pragma unroll
    for (int i = 0; i < 4; i++)
        #pragma unroll
        for (int j = 0; j < 4; j++)
            #pragma unroll
            for (int r = 0; r < 4; r++) acc[i][j][r] = 0.f;

    uint4 qh[4], kh[4];

    #define QK_LDG(kk) do {                                                    \
        _Pragma("unroll")                                                      \
        for (int i_ = 0; i_ < 4; i_++) {                                       \
            int r_ = lr + i_ * 32;                                             \
            const float* pq = Qb + (size_t)r_ * D_ + (kk) + lc * 8;            \
            float4 x = *reinterpret_cast<const float4*>(pq);                   \
            float4 y = *reinterpret_cast<const float4*>(pq + 4);               \
            qh[i_].x = f2h2(x.x, x.y); qh[i_].y = f2h2(x.z, x.w);              \
            qh[i_].z = f2h2(y.x, y.y); qh[i_].w = f2h2(y.z, y.w);              \
            const float* pk = Kb + (size_t)r_ * D_ + (kk) + lc * 8;            \
            x = *reinterpret_cast<const float4*>(pk);                          \
            y = *reinterpret_cast<const float4*>(pk + 4);                      \
            kh[i_].x = f2h2(x.x, x.y); kh[i_].y = f2h2(x.z, x.w);              \
            kh[i_].z = f2h2(y.x, y.y); kh[i_].w = f2h2(y.z, y.w);              \
        }                                                                      \
    } while (0)

    #define QK_STS(st) do {                                                    \
        uint32_t bA_ = smem_u + (uint32_t)(st) * 32768u;                       \
        uint32_t bB_ = bA_ + 16384u;                                           \
        _Pragma("unroll")                                                      \
        for (int i_ = 0; i_ < 4; i_++) {                                       \
            uint32_t off_ = (uint32_t)((lr + i_ * 32) * 128) + psw;            \
            asm volatile("st.shared.v4.b32 [%0], {%1,%2,%3,%4};" ::            \
                "r"(bA_ + off_), "r"(qh[i_].x), "r"(qh[i_].y),                 \
                "r"(qh[i_].z), "r"(qh[i_].w) : "memory");                      \
            asm volatile("st.shared.v4.b32 [%0], {%1,%2,%3,%4};" ::            \
                "r"(bB_ + off_), "r"(kh[i_].x), "r"(kh[i_].y),                 \
                "r"(kh[i_].z), "r"(kh[i_].w) : "memory");                      \
        }                                                                      \
    } while (0)

    QK_LDG(0);
    QK_STS(0);
    QK_LDG(64);
    __syncthreads();

    for (int t = 0; t < 8; t++) {                // D/64 = 8 k-tiles
        const uint32_t bA = smem_u + (uint32_t)(t % 3) * 32768u;
        const uint32_t bB = bA + 16384u;

        if (t + 1 < 8) {
            QK_STS((t + 1) % 3);
            if (t + 2 < 8) QK_LDG((t + 2) * 64);
        }

        #pragma unroll
        for (int ks = 0; ks < 4; ks++) {         // 4 x k16 per tile
            uint32_t bf[4][2];
            #pragma unroll
            for (int in_ = 0; in_ < 4; in_++) {
                int n = wn * 32 + in_ * 8 + l7;
                uint32_t addr = bB + (uint32_t)(n * 128)
                              + (uint32_t)((((ks << 1) + lb1) ^ l7) << 4);
                ldsm2(bf[in_][0], bf[in_][1], addr);
            }
            #pragma unroll
            for (int im = 0; im < 4; im++) {
                int r = wm * 64 + im * 16 + l7 + lb1 * 8;
                uint32_t addr = bA + (uint32_t)(r * 128)
                              + (uint32_t)((((ks << 1) + lb2) ^ l7) << 4);
                uint32_t a[4];
                ldsm4(a[0], a[1], a[2], a[3], addr);
                #pragma unroll
                for (int in_ = 0; in_ < 4; in_++)
                    mma_f16(acc[im][in_], a, bf[in_]);
            }
        }
        __syncthreads();
    }
    #undef QK_LDG
    #undef QK_STS

    // Epilogue: scale + mask, write masked_vec.
    const int* repb = rep + b * S_;
    #pragma unroll
    for (int im = 0; im < 4; im++) {
        int mA = m0 + wm * 64 + im * 16 + gID;
        int mB = mA + 8;
        int rqA = repb[mA], rqB = repb[mB];
        #pragma unroll
        for (int in_ = 0; in_ < 4; in_++) {
            int n = n0 + wn * 32 + in_ * 8 + tig * 2;
            int rk0 = repb[n], rk1 = repb[n + 1];
            float v00 = acc[im][in_][0] * SCALE;
            float v01 = acc[im][in_][1] * SCALE;
            float v10 = acc[im][in_][2] * SCALE;
            float v11 = acc[im][in_][3] * SCALE;
            attn_b[(size_t)mA * S_ + n]     = (n     < mA && rqA && rk0) ? v00 : 0.f;
            attn_b[(size_t)mA * S_ + n + 1] = (n + 1 < mA && rqA && rk1) ? v01 : 0.f;
            attn_b[(size_t)mB * S_ + n]     = (n     < mB && rqB && rk0) ? v10 : 0.f;
            attn_b[(size_t)mB * S_ + n + 1] = (n + 1 < mB && rqB && rk1) ? v11 : 0.f;
        }
    }
}

// ---------------------------------------------------------------------------
// Kernel 2: in-place row softmax, TRIANGULAR: only k < q is read/written.
// Upper region already holds exact zeros from qk (= its softmax value).
// max init 0 is exact: every row has a structural zero at k >= q.
// ---------------------------------------------------------------------------
__global__ __launch_bounds__(256) void softmax_kernel(
    float* attn_param, const int* __restrict__ rep)
{
    float* attn = attn_param ? attn_param : g_attn_scratch;
    const int q = blockIdx.x, b = blockIdx.y;
    if (q == 0) return;                        // row 0: all masked, already 0
    float* row = attn + ((size_t)b * S_ + q) * S_;
    const int tid = threadIdx.x;
    const int k0 = tid * 4;
    const bool active = (k0 < q);

    float4 v = make_float4(0.f, 0.f, 0.f, 0.f);
    int4 rk = make_int4(0, 0, 0, 0);
    if (active) {
        v = reinterpret_cast<float4*>(row)[tid];
        rk = reinterpret_cast<const int4*>(rep + b * S_)[tid];
    }
    const int rq = rep[b * S_ + q];

    __shared__ float red_max[8];
    __shared__ float red_sum[8];

    float mx = fmaxf(fmaxf(fmaxf(v.x, v.y), fmaxf(v.z, v.w)), 0.f);
    #pragma unroll
    for (int o = 16; o; o >>= 1) mx = fmaxf(mx, __shfl_xor_sync(0xffffffffu, mx, o));
    if ((tid & 31) == 0) red_max[tid >> 5] = mx;
    __syncthreads();
    mx = red_max[0];
    #pragma unroll
    for (int w = 1; w < 8; w++) mx = fmaxf(mx, red_max[w]);

    const bool m0b = (k0     < q) && rq && rk.x;
    const bool m1b = (k0 + 1 < q) && rq && rk.y;
    const bool m2b = (k0 + 2 < q) && rq && rk.z;
    const bool m3b = (k0 + 3 < q) && rq && rk.w;
    float e0 = m0b ? __expf(v.x - mx) : 0.f;
    float e1 = m1b ? __expf(v.y - mx) : 0.f;
    float e2 = m2b ? __expf(v.z - mx) : 0.f;
    float e3 = m3b ? __expf(v.w - mx) : 0.f;

    float sden = (e0 + e1) + (e2 + e3);
    #pragma unroll
    for (int o = 16; o; o >>= 1) sden += __shfl_xor_sync(0xffffffffu, sden, o);
    if ((tid & 31) == 0) red_sum[tid >> 5] = sden;
    __syncthreads();
    sden = red_sum[0];
    #pragma unroll
    for (int w = 1; w < 8; w++) sden += red_sum[w];

    float s2 = sden + ((sden == 0.f) ? 1.f : 0.f);
    float inv = 1.f / (s2 + 1e-20f);

    if (active) {
        v.x = e0 * inv; v.y = e1 * inv; v.z = e2 * inv; v.w = e3 * inv;
        reinterpret_cast<float4*>(row)[tid] = v;
    }
}

// ---------------------------------------------------------------------------
// Kernel 3: out = attn_sm @ V.  fp16 m16n8k16, BK=64, triangular K-loop.
// A (attn) K-major like Q; V is [k][n] n-contiguous -> trans ldmatrix for B.
// ---------------------------------------------------------------------------
__global__ __launch_bounds__(256, 2) void pv_kernel(
    const float* attn_param, const float* __restrict__ V, float* __restrict__ out)
{
    const float* attn = attn_param ? attn_param : g_attn_scratch;
    const int bm = blockIdx.y, bn = blockIdx.x, b = blockIdx.z;
    const int m0 = bm * 128, n0 = bn * 128;
    const int tid = threadIdx.x;

    extern __shared__ float smem[];              // 3 stages x 32KB (A16K + V16K)
    const uint32_t smem_u = (uint32_t)__cvta_generic_to_shared(smem);

    const int warp = tid >> 5, lane = tid & 31;
    const int wm = warp & 1, wn = warp >> 1;
    const int gID = lane >> 2, tig = lane & 3;

    const float* Ab = attn + ((size_t)b * S_ + m0) * S_;
    const float* Vb = V + (size_t)b * S_ * D_;

    // A producer: like qk (rows lr+32i, chunk lc)
    const int lr = tid >> 3, lc = tid & 7;
    const uint32_t psw = (uint32_t)((lc ^ (lr & 7)) << 4);
    // V producer: 16 threads per 512B f32 row; fp16 row = 256B = 16 chunks
    const int vr = tid >> 4, vc = tid & 15;
    const uint32_t vsw = (uint32_t)((vc ^ (vr & 7)) << 4);

    const int l7 = lane & 7;
    const int lb1 = (lane >> 3) & 1;
    const int lb2 = lane >> 4;

    float acc[4][4][4];
    #pragma unroll
    for (int i = 0; i < 4; i++)
        #pragma unroll
        for (int j = 0; j < 4; j++)
            #pragma unroll
            for (int r = 0; r < 4; r++) acc[i][j][r] = 0.f;

    const int NT = (bm + 1) * 2;     // k-tiles of 64 f32, strictly-lower bound

    uint4 ah[4], vh[4];

    #define PV_LDG(kk) do {                                                    \
        _Pragma("unroll")                                                      \
        for (int i_ = 0; i_ < 4; i_++) {                                       \
            int r_ = lr + i_ * 32;                                             \
            const float* pa = Ab + (size_t)r_ * S_ + (kk) + lc * 8;            \
            float4 x = *reinterpret_cast<const float4*>(pa);                   \
            float4 y = *reinterpret_cast<const float4*>(pa + 4);               \
            ah[i_].x = f2h2(x.x, x.y); ah[i_].y = f2h2(x.z, x.w);              \
            ah[i_].z = f2h2(y.x, y.y); ah[i_].w = f2h2(y.z, y.w);              \
            int kr_ = vr + i_ * 16;                                            \
            const float* pv = Vb + (size_t)((kk) + kr_) * D_ + n0 + vc * 8;    \
            x = *reinterpret_cast<const float4*>(pv);                          \
            y = *reinterpret_cast<const float4*>(pv + 4);                      \
            vh[i_].x = f2h2(x.x, x.y); vh[i_].y = f2h2(x.z, x.w);              \
            vh[i_].z = f2h2(y.x, y.y); vh[i_].w = f2h2(y.z, y.w);              \
        }                                                                      \
    } while (0)

    #define PV_STS(st) do {                                                    \
        uint32_t bA_ = smem_u + (uint32_t)(st) * 32768u;                       \
        uint32_t bV_ = bA_ + 16384u;                                           \
        _Pragma("unroll")                                                      \
        for (int i_ = 0; i_ < 4; i_++) {                                       \
            uint32_t offA_ = (uint32_t)((lr + i_ * 32) * 128) + psw;           \
            asm volatile("st.shared.v4.b32 [%0], {%1,%2,%3,%4};" ::            \
                "r"(bA_ + offA_), "r"(ah[i_].x), "r"(ah[i_].y),                \
                "r"(ah[i_].z), "r"(ah[i_].w) : "memory");                      \
            uint32_t offV_ = (uint32_t)((vr + i_ * 16) * 256) + vsw;           \
            asm volatile("st.shared.v4.b32 [%0], {%1,%2,%3,%4};" ::            \
                "r"(bV_ + offV_), "r"(vh[i_].x), "r"(vh[i_].y),                \
                "r"(vh[i_].z), "r"(vh[i_].w) : "memory");                      \
        }                                                                      \
    } while (0)

    PV_LDG(0);
    PV_STS(0);
    PV_LDG(64);                      // NT >= 2 always
    __syncthreads();

    for (int t = 0; t < NT; t++) {
        const uint32_t bA = smem_u + (uint32_t)(t % 3) * 32768u;
        const uint32_t bV = bA + 16384u;

        if (t + 1 < NT) {
            PV_STS((t + 1) % 3);
            if (t + 2 < NT) PV_LDG((t + 2) * 64);
        }

        #pragma unroll
        for (int ks = 0; ks < 4; ks++) {
            uint32_t bf[4][2];
            #pragma unroll
            for (int in_ = 0; in_ < 4; in_++) {
                int nch = wn * 4 + in_;
                int kr = ks * 16 + l7 + lb1 * 8;
                uint32_t addr = bV + (uint32_t)(kr * 256)
                              + (uint32_t)((nch ^ l7) << 4);
                ldsm2t(bf[in_][0], bf[in_][1], addr);
            }
            #pragma unroll
            for (int im = 0; im < 4; im++) {
                int r = wm * 64 + im * 16 + l7 + lb1 * 8;
                uint32_t addr = bA + (uint32_t)(r * 128)
                              + (uint32_t)((((ks << 1) + lb2) ^ l7) << 4);
                uint32_t a[4];
                ldsm4(a[0], a[1], a[2], a[3], addr);
                #pragma unroll
                for (int in_ = 0; in_ < 4; in_++)
                    mma_f16(acc[im][in_], a, bf[in_]);
            }
        }
        __syncthreads();
    }
    #undef PV_LDG
    #undef PV_STS

    #pragma unroll
    for (int im = 0; im < 4; im++) {
        int mA = m0 + wm * 64 + im * 16 + gID;
        int mB = mA + 8;
        #pragma unroll
        for (int in_ = 0; in_ < 4; in_++) {
            int n = n0 + wn * 32 + in_ * 8 + tig * 2;
            out[((size_t)b * S_ + mA) * D_ + n]     = acc[im][in_][0];
            out[((size_t)b * S_ + mA) * D_ + n + 1] = acc[im][in_][1];
            out[((size_t)b * S_ + mB) * D_ + n]     = acc[im][in_][2];
            out[((size_t)b * S_ + mB) * D_ + n + 1] = acc[im][in_][3];
        }
    }
}

extern "C" void kernel_launch(void* const* d_in, const int* in_sizes, int n_in,
                              void* d_out, int out_size)
{
    const float* q   = (const float*)d_in[0];
    const float* k   = (const float*)d_in[1];
    const float* v   = (const float*)d_in[2];
    const int*   rep = (const int*)d_in[3];
    float* out = (float*)d_out;

    const long OUT_ELEMS  = (long)B_ * S_ * D_;   // 16,777,216
    const long ATTN_ELEMS = (long)B_ * S_ * S_;   // 33,554,432

    float* attn = nullptr;  // nullptr -> kernels fall back to g_attn_scratch
    if ((long)out_size >= OUT_ELEMS + ATTN_ELEMS)
        attn = out + OUT_ELEMS;

    const int SMEM3 = 3 * 32768;   // 98304 B for both GEMM kernels
    cudaFuncSetAttribute(qk_kernel, cudaFuncAttributeMaxDynamicSharedMemorySize, SMEM3);
    cudaFuncSetAttribute(pv_kernel, cudaFuncAttributeMaxDynamicSharedMemorySize, SMEM3);

    dim3 g1(8, 8, B_);
    qk_kernel<<<g1, 256, SMEM3>>>(q, k, rep, attn);

    dim3 g2(S_, B_);
    softmax_kernel<<<g2, 256>>>(attn, rep);

    dim3 g3(4, 8, B_);
    pv_kernel<<<g3, 256, SMEM3>>>(attn, v, out);
}